// round 2
// baseline (speedup 1.0000x reference)
#include <cuda_runtime.h>
#include <cstddef>

// Problem constants
#define K_CB   2048
#define D_DIM  512
#define B_DIM  16
#define N_DIM  8192
#define M_ROWS (B_DIM * N_DIM)   // 131072

// Tiling for the distance kernel
#define BM 128
#define BK 128
#define BD 16

// Scratch (no allocations allowed): codebook squared norms + int indices
__device__ float g_e2[K_CB];
__device__ int   g_ind[M_ROWS];

// ---------------------------------------------------------------------------
// Kernel 1: e2[k] = sum_d embed[k][d]^2
// ---------------------------------------------------------------------------
__global__ __launch_bounds__(128) void e2_kernel(const float* __restrict__ embed) {
    int k = blockIdx.x;
    const float* row = embed + (size_t)k * D_DIM;
    float s = 0.f;
    for (int d = threadIdx.x; d < D_DIM; d += 128) {
        float v = row[d];
        s += v * v;
    }
    #pragma unroll
    for (int o = 16; o > 0; o >>= 1) s += __shfl_down_sync(0xffffffffu, s, o);
    __shared__ float ws[4];
    if ((threadIdx.x & 31) == 0) ws[threadIdx.x >> 5] = s;
    __syncthreads();
    if (threadIdx.x == 0) g_e2[k] = ws[0] + ws[1] + ws[2] + ws[3];
}

// ---------------------------------------------------------------------------
// Kernel 2: fused scores + argmax.
//   Rows m = b*N + n (x stored [B, D, N] so a row tile = 128 consecutive n).
//   score[m,k] = 2 * dot(x_m, e_k) - e2[k];  track running argmax per row.
//   128x128 score tile per block, D tiled by 16, 256 threads, 8x8 micro-tile.
// ---------------------------------------------------------------------------
__global__ __launch_bounds__(256) void dist_kernel(const float* __restrict__ x,
                                                   const float* __restrict__ embed,
                                                   float* __restrict__ out_ind_f) {
    __shared__ float As[BD][BM];        // x tile, d-major
    __shared__ float Bs[BD][BK + 4];    // embed tile, d-major, padded
    __shared__ float sBest[BM][16];
    __shared__ int   sIdx[BM][16];

    const int m0 = blockIdx.x * BM;
    const int bb = m0 / N_DIM;
    const int n0 = m0 % N_DIM;
    const float* xbase = x + (size_t)bb * D_DIM * N_DIM + n0;

    const int tid = threadIdx.x;
    const int tr  = tid >> 4;   // 0..15 : row group (8 rows each)
    const int tc  = tid & 15;   // 0..15 : col group (8 cols each)

    float best[8];
    int   bidx[8];
    #pragma unroll
    for (int i = 0; i < 8; i++) { best[i] = -3.0e38f; bidx[i] = 0; }

    for (int kt = 0; kt < K_CB; kt += BK) {
        float acc[8][8];
        #pragma unroll
        for (int i = 0; i < 8; i++)
            #pragma unroll
            for (int j = 0; j < 8; j++) acc[i][j] = 0.f;

        for (int dt = 0; dt < D_DIM; dt += BD) {
            // Load x tile: 2048 elements, coalesced over n
            #pragma unroll
            for (int l = 0; l < 8; l++) {
                int i = tid + l * 256;
                int r = i & (BM - 1);
                int d = i >> 7;
                As[d][r] = xbase[(size_t)(dt + d) * N_DIM + r];
            }
            // Load embed tile: 2048 elements, 16-wide segments per codeword
            #pragma unroll
            for (int l = 0; l < 8; l++) {
                int i = tid + l * 256;
                int d = i & (BD - 1);
                int k = i >> 4;
                Bs[d][k] = embed[(size_t)(kt + k) * D_DIM + dt + d];
            }
            __syncthreads();

            #pragma unroll
            for (int dd = 0; dd < BD; dd++) {
                float4 a0 = *(const float4*)&As[dd][tr * 8];
                float4 a1 = *(const float4*)&As[dd][tr * 8 + 4];
                float4 b0 = *(const float4*)&Bs[dd][tc * 8];
                float4 b1 = *(const float4*)&Bs[dd][tc * 8 + 4];
                float a[8] = {a0.x, a0.y, a0.z, a0.w, a1.x, a1.y, a1.z, a1.w};
                float b[8] = {b0.x, b0.y, b0.z, b0.w, b1.x, b1.y, b1.z, b1.w};
                #pragma unroll
                for (int i = 0; i < 8; i++)
                    #pragma unroll
                    for (int j = 0; j < 8; j++)
                        acc[i][j] += a[i] * b[j];
            }
            __syncthreads();
        }

        // Fold this k-tile into the running argmax (ascending k + strict '>'
        // keeps the lowest index on ties, matching jnp.argmax).
        #pragma unroll
        for (int j = 0; j < 8; j++) {
            int k = kt + tc * 8 + j;
            float e2v = g_e2[k];
            #pragma unroll
            for (int i = 0; i < 8; i++) {
                float s = 2.0f * acc[i][j] - e2v;
                if (s > best[i]) { best[i] = s; bidx[i] = k; }
            }
        }
    }

    // Cross-thread (over tc) argmax reduce per row
    #pragma unroll
    for (int i = 0; i < 8; i++) {
        sBest[tr * 8 + i][tc] = best[i];
        sIdx [tr * 8 + i][tc] = bidx[i];
    }
    __syncthreads();
    if (tid < BM) {
        float bv = sBest[tid][0];
        int   bi = sIdx[tid][0];
        #pragma unroll
        for (int t = 1; t < 16; t++) {
            float v  = sBest[tid][t];
            int   vi = sIdx[tid][t];
            if (v > bv || (v == bv && vi < bi)) { bv = v; bi = vi; }
        }
        int m = m0 + tid;
        g_ind[m] = bi;
        out_ind_f[m] = (float)bi;
    }
}

// ---------------------------------------------------------------------------
// Kernel 3: quantize[b, d, n] = embed[ind[b,n], d] via transpose-through-smem.
// One block handles (b, 32 consecutive n) x full D.
// ---------------------------------------------------------------------------
__global__ __launch_bounds__(256) void gather_kernel(const float* __restrict__ embed,
                                                     float* __restrict__ out) {
    extern __shared__ float tile[];     // [32][513]
    __shared__ int inds[32];
    const int bb = blockIdx.y;
    const int n0 = blockIdx.x * 32;

    if (threadIdx.x < 32) inds[threadIdx.x] = g_ind[bb * N_DIM + n0 + threadIdx.x];
    __syncthreads();

    // Phase 1: load 32 codebook rows, coalesced over d
    for (int i = threadIdx.x; i < 32 * D_DIM; i += 256) {
        int n = i >> 9;          // /512
        int d = i & (D_DIM - 1);
        tile[n * 513 + d] = embed[(size_t)inds[n] * D_DIM + d];
    }
    __syncthreads();

    // Phase 2: write transposed, coalesced over n (128B per warp)
    float* obase = out + (size_t)bb * D_DIM * N_DIM + n0;
    for (int i = threadIdx.x; i < 32 * D_DIM; i += 256) {
        int n = i & 31;
        int d = i >> 5;
        obase[(size_t)d * N_DIM + n] = tile[n * 513 + d];
    }
}

// ---------------------------------------------------------------------------
extern "C" void kernel_launch(void* const* d_in, const int* in_sizes, int n_in,
                              void* d_out, int out_size) {
    const float* x     = (const float*)d_in[0];   // [B, D, N] f32
    const float* embed = (const float*)d_in[1];   // [K, D]    f32
    float* out   = (float*)d_out;
    float* out_q = out;                                   // [B, D, N]
    float* out_i = out + (size_t)B_DIM * D_DIM * N_DIM;   // [B, N] indices as f32

    (void)in_sizes; (void)n_in; (void)out_size;

    static const int gather_smem = 32 * 513 * (int)sizeof(float);  // 65664 B
    cudaFuncSetAttribute(gather_kernel, cudaFuncAttributeMaxDynamicSharedMemorySize,
                         gather_smem);

    e2_kernel<<<K_CB, 128>>>(embed);
    dist_kernel<<<M_ROWS / BM, 256>>>(x, embed, out_i);
    gather_kernel<<<dim3(N_DIM / 32, B_DIM), 256, gather_smem>>>(embed, out_q);
}

// round 4
// speedup vs baseline: 2.3240x; 2.3240x over previous
#include <cuda_runtime.h>
#include <cuda_bf16.h>
#include <cstdint>
#include <cstddef>

#define K_CB   2048
#define D_DIM  512
#define B_DIM  16
#define N_DIM  8192
#define M_ROWS (B_DIM * N_DIM)
#define MARGIN 1.0e-2f

// -------- device scratch (no allocations allowed) --------
__device__ uint32_t g_Ail[(size_t)M_ROWS * 512];  // packed (hi | lo<<16) bf16 per dim
__device__ uint32_t g_Bil[(size_t)K_CB * 512];
__device__ uint32_t g_Bsw[(size_t)K_CB * 512];    // hi/lo swapped
__device__ float    g_e2[K_CB];
__device__ int      g_ind[M_ROWS];
__device__ int      g_flag[M_ROWS];
__device__ int      g_nflag;

// -------- helpers --------
__device__ __forceinline__ uint32_t smem_u32(const void* p) {
    uint32_t a;
    asm("{ .reg .u64 t; cvta.to.shared.u64 t, %1; cvt.u32.u64 %0, t; }" : "=r"(a) : "l"(p));
    return a;
}
#define CP_A16(s, g) \
    asm volatile("cp.async.cg.shared.global [%0], [%1], 16;" :: "r"(s), "l"(g) : "memory")
#define CP_COMMIT() asm volatile("cp.async.commit_group;" ::: "memory")
#define CP_WAIT(n)  asm volatile("cp.async.wait_group %0;" :: "n"(n) : "memory")

__device__ __forceinline__ void ldsm4(uint32_t* r, uint32_t addr) {
    asm volatile("ldmatrix.sync.aligned.m8n8.x4.shared.b16 {%0,%1,%2,%3}, [%4];"
                 : "=r"(r[0]), "=r"(r[1]), "=r"(r[2]), "=r"(r[3]) : "r"(addr));
}
__device__ __forceinline__ void mma16816(float* c, const uint32_t* a, const uint32_t* b) {
    asm volatile("mma.sync.aligned.m16n8k16.row.col.f32.bf16.bf16.f32 "
                 "{%0,%1,%2,%3}, {%4,%5,%6,%7}, {%8,%9}, {%0,%1,%2,%3};"
                 : "+f"(c[0]), "+f"(c[1]), "+f"(c[2]), "+f"(c[3])
                 : "r"(a[0]), "r"(a[1]), "r"(a[2]), "r"(a[3]), "r"(b[0]), "r"(b[1]));
}
__device__ __forceinline__ uint32_t pack_hl(float v) {
    __nv_bfloat16 h = __float2bfloat16(v);
    float hf = __bfloat162float(h);
    __nv_bfloat16 l = __float2bfloat16(v - hf);
    return (uint32_t)__bfloat16_as_ushort(h) | ((uint32_t)__bfloat16_as_ushort(l) << 16);
}

// -------- prep: codebook split + e2 --------
__global__ __launch_bounds__(128) void prep_embed_kernel(const float* __restrict__ embed) {
    int k = blockIdx.x;
    const float* row = embed + (size_t)k * D_DIM;
    uint32_t* bil = g_Bil + (size_t)k * D_DIM;
    uint32_t* bsw = g_Bsw + (size_t)k * D_DIM;
    float s = 0.f;
    for (int d = threadIdx.x; d < D_DIM; d += 128) {
        float v = row[d];
        s += v * v;
        uint32_t p = pack_hl(v);
        bil[d] = p;
        bsw[d] = (p >> 16) | (p << 16);
    }
    #pragma unroll
    for (int o = 16; o > 0; o >>= 1) s += __shfl_down_sync(0xffffffffu, s, o);
    __shared__ float ws[4];
    if ((threadIdx.x & 31) == 0) ws[threadIdx.x >> 5] = s;
    __syncthreads();
    if (threadIdx.x == 0) g_e2[k] = ws[0] + ws[1] + ws[2] + ws[3];
    if (blockIdx.x == 0 && threadIdx.x == 0) g_nflag = 0;
}

// -------- prep: x[B,D,N] -> g_Ail[m][d] packed (transpose through smem) --------
__global__ __launch_bounds__(256) void prep_x_kernel(const float* __restrict__ x) {
    __shared__ uint32_t t[64][65];
    int b = blockIdx.y, n0 = blockIdx.x * 64;
    const float* xb = x + (size_t)b * D_DIM * N_DIM + n0;
    for (int dc = 0; dc < 8; dc++) {
        __syncthreads();
        #pragma unroll
        for (int l = 0; l < 16; l++) {
            int i = threadIdx.x + l * 256;
            int dd = i >> 6, nn = i & 63;
            t[dd][nn] = pack_hl(xb[(size_t)(dc * 64 + dd) * N_DIM + nn]);
        }
        __syncthreads();
        #pragma unroll
        for (int l = 0; l < 16; l++) {
            int i = threadIdx.x + l * 256;
            int nn = i >> 6, dd = i & 63;
            g_Ail[(size_t)(b * N_DIM + n0 + nn) * 512 + dc * 64 + dd] = t[dd][nn];
        }
    }
}

// -------- tile loader: 3x (128 rows x 128B), swizzled, via cp.async --------
#define STAGE_BYTES 49152
__device__ __forceinline__ void load_tiles(uint32_t ss, const uint4* Ag, const uint4* Bi,
                                           const uint4* Bs, int kb, int tid) {
    #pragma unroll
    for (int l = 0; l < 4; l++) {
        int i = tid + l * 256;
        int row = i >> 3, ch = i & 7;
        uint32_t soff = (uint32_t)row * 128 + (uint32_t)((ch ^ (row & 7)) << 4);
        size_t goff = (size_t)row * 128 + (size_t)kb * 8 + ch;
        CP_A16(ss + soff,         Ag + goff);
        CP_A16(ss + 16384 + soff, Bi + goff);
        CP_A16(ss + 32768 + soff, Bs + goff);
    }
}

// -------- warp-tile compute: 32x64 per warp, K=64 bf16 (x2 variants) --------
__device__ __forceinline__ void compute_stage(uint32_t ss, int lane, int wm, int wn,
                                              float acc[2][8][4]) {
    uint32_t sA = ss, sBi = ss + 16384, sBs = ss + 32768;
    #pragma unroll
    for (int kk = 0; kk < 4; kk++) {
        uint32_t a[2][4];
        #pragma unroll
        for (int i = 0; i < 2; i++) {
            int r = wm * 32 + i * 16 + (lane & 15);
            int c = (kk * 2 + (lane >> 4)) ^ (r & 7);
            ldsm4(a[i], sA + r * 128 + c * 16);
        }
        #pragma unroll
        for (int v = 0; v < 2; v++) {
            uint32_t bb = v ? sBs : sBi;
            #pragma unroll
            for (int j16 = 0; j16 < 4; j16++) {
                int n = wn * 64 + j16 * 16 + (lane & 7) + ((lane >> 4) << 3);
                int c = (kk * 2 + ((lane >> 3) & 1)) ^ (n & 7);
                uint32_t b[4];
                ldsm4(b, bb + n * 128 + c * 16);
                #pragma unroll
                for (int i = 0; i < 2; i++) {
                    mma16816(acc[i][j16 * 2 + 0], a[i], b + 0);
                    mma16816(acc[i][j16 * 2 + 1], a[i], b + 2);
                }
            }
        }
    }
}

// -------- main dist+argmax kernel --------
__global__ void __launch_bounds__(256, 2) vq_dist_kernel(float* __restrict__ out_ind_f) {
    extern __shared__ char smem[];
    __shared__ float sB1[2][128];
    __shared__ float sB2[2][128];
    __shared__ int   sIx[2][128];
    uint32_t sb = smem_u32(smem);
    const int tid = threadIdx.x, lane = tid & 31, wid = tid >> 5;
    const int wm = wid & 3, wn = wid >> 2;
    const int m0 = blockIdx.x * 128;
    const uint4* Ag = (const uint4*)(g_Ail + (size_t)m0 * 512);

    float best1[4], best2[4];
    int   bidx[4];
    #pragma unroll
    for (int r = 0; r < 4; r++) { best1[r] = -3.0e38f; best2[r] = -3.0e38f; bidx[r] = 0; }

    for (int nt = 0; nt < 16; nt++) {
        const uint4* Bi = (const uint4*)(g_Bil + (size_t)nt * 128 * 512);
        const uint4* Bs = (const uint4*)(g_Bsw + (size_t)nt * 128 * 512);

        float acc[2][8][4];
        #pragma unroll
        for (int i = 0; i < 2; i++)
            #pragma unroll
            for (int j = 0; j < 8; j++)
                #pragma unroll
                for (int q = 0; q < 4; q++) acc[i][j][q] = 0.f;

        load_tiles(sb, Ag, Bi, Bs, 0, tid);
        CP_COMMIT();
        for (int kb = 0; kb < 16; kb++) {
            uint32_t cur = sb + (kb & 1) * STAGE_BYTES;
            if (kb < 15) {
                load_tiles(sb + ((kb + 1) & 1) * STAGE_BYTES, Ag, Bi, Bs, kb + 1, tid);
                CP_COMMIT();
                CP_WAIT(1);
            } else {
                CP_WAIT(0);
            }
            __syncthreads();
            compute_stage(cur, lane, wm, wn, acc);
            __syncthreads();
        }

        // fold scores into running top-2 (ascending k => strict '>' keeps lowest idx)
        #pragma unroll
        for (int j = 0; j < 8; j++) {
            int kb_ = nt * 128 + wn * 64 + j * 8 + (lane & 3) * 2;
            float e2a = g_e2[kb_], e2b = g_e2[kb_ + 1];
            #pragma unroll
            for (int i = 0; i < 2; i++) {
                float s0 = 2.f * acc[i][j][0] - e2a;
                float s1 = 2.f * acc[i][j][1] - e2b;
                float s2 = 2.f * acc[i][j][2] - e2a;
                float s3 = 2.f * acc[i][j][3] - e2b;
                int r0 = i * 2, r1 = i * 2 + 1;
                if (s0 > best1[r0]) { best2[r0] = best1[r0]; best1[r0] = s0; bidx[r0] = kb_; }
                else if (s0 > best2[r0]) best2[r0] = s0;
                if (s1 > best1[r0]) { best2[r0] = best1[r0]; best1[r0] = s1; bidx[r0] = kb_ + 1; }
                else if (s1 > best2[r0]) best2[r0] = s1;
                if (s2 > best1[r1]) { best2[r1] = best1[r1]; best1[r1] = s2; bidx[r1] = kb_; }
                else if (s2 > best2[r1]) best2[r1] = s2;
                if (s3 > best1[r1]) { best2[r1] = best1[r1]; best1[r1] = s3; bidx[r1] = kb_ + 1; }
                else if (s3 > best2[r1]) best2[r1] = s3;
            }
        }
    }

    // reduce across the 4 lanes sharing each row
    #pragma unroll
    for (int o = 1; o < 4; o <<= 1) {
        #pragma unroll
        for (int r = 0; r < 4; r++) {
            float ob1 = __shfl_xor_sync(0xffffffffu, best1[r], o);
            float ob2 = __shfl_xor_sync(0xffffffffu, best2[r], o);
            int   oi  = __shfl_xor_sync(0xffffffffu, bidx[r], o);
            float nb2 = fmaxf(fminf(best1[r], ob1), fmaxf(best2[r], ob2));
            if (ob1 > best1[r] || (ob1 == best1[r] && oi < bidx[r])) {
                best1[r] = ob1; bidx[r] = oi;
            }
            best2[r] = nb2;
        }
    }
    if ((lane & 3) == 0) {
        #pragma unroll
        for (int r = 0; r < 4; r++) {
            int row = wm * 32 + (r >> 1) * 16 + (r & 1) * 8 + (lane >> 2);
            sB1[wn][row] = best1[r];
            sB2[wn][row] = best2[r];
            sIx[wn][row] = bidx[r];
        }
    }
    __syncthreads();
    if (tid < 128) {
        float a1 = sB1[0][tid], b1 = sB1[1][tid];
        float a2 = sB2[0][tid], b2 = sB2[1][tid];
        int   ai = sIx[0][tid], bi = sIx[1][tid];
        float f2 = fmaxf(fminf(a1, b1), fmaxf(a2, b2));
        float f1; int fi;
        if (b1 > a1 || (b1 == a1 && bi < ai)) { f1 = b1; fi = bi; }
        else { f1 = a1; fi = ai; }
        int m = m0 + tid;
        g_ind[m] = fi;
        out_ind_f[m] = (float)fi;
        if (f1 - f2 < MARGIN) {
            int slot = atomicAdd(&g_nflag, 1);
            g_flag[slot] = m;
        }
    }
}

// -------- exact fp32 fallback for flagged rows --------
__global__ __launch_bounds__(256) void fallback_kernel(const float* __restrict__ x,
                                                       const float* __restrict__ embed,
                                                       float* __restrict__ out_ind_f) {
    __shared__ float xr[D_DIM];
    __shared__ float wbest[8];
    __shared__ int   widx[8];
    int nf = g_nflag;
    for (int f = blockIdx.x; f < nf; f += gridDim.x) {
        int m = g_flag[f];
        int b = m / N_DIM, n = m % N_DIM;
        for (int d = threadIdx.x; d < D_DIM; d += 256)
            xr[d] = x[(size_t)b * D_DIM * N_DIM + (size_t)d * N_DIM + n];
        __syncthreads();
        int wd = threadIdx.x >> 5, ld = threadIdx.x & 31;
        float best = -3.0e38f; int bi = 0;
        for (int k = wd; k < K_CB; k += 8) {
            const float* er = embed + (size_t)k * D_DIM;
            float s = 0.f;
            for (int d = ld; d < D_DIM; d += 32) s += xr[d] * er[d];
            #pragma unroll
            for (int o = 16; o > 0; o >>= 1) s += __shfl_down_sync(0xffffffffu, s, o);
            s = __shfl_sync(0xffffffffu, s, 0);
            float sc = 2.0f * s - g_e2[k];
            if (sc > best) { best = sc; bi = k; }
        }
        if (ld == 0) { wbest[wd] = best; widx[wd] = bi; }
        __syncthreads();
        if (threadIdx.x == 0) {
            float bv = wbest[0]; int bix = widx[0];
            #pragma unroll
            for (int w = 1; w < 8; w++)
                if (wbest[w] > bv || (wbest[w] == bv && widx[w] < bix)) { bv = wbest[w]; bix = widx[w]; }
            g_ind[m] = bix;
            out_ind_f[m] = (float)bix;
        }
        __syncthreads();
    }
}

// -------- gather: out[b,d,n] = embed[ind[b,n], d] --------
__global__ __launch_bounds__(256) void gather_kernel(const float* __restrict__ embed,
                                                     float* __restrict__ out) {
    extern __shared__ float tile[];
    __shared__ int inds[32];
    const int bb = blockIdx.y;
    const int n0 = blockIdx.x * 32;
    if (threadIdx.x < 32) inds[threadIdx.x] = g_ind[bb * N_DIM + n0 + threadIdx.x];
    __syncthreads();
    for (int i = threadIdx.x; i < 32 * D_DIM; i += 256) {
        int n = i >> 9, d = i & (D_DIM - 1);
        tile[n * 513 + d] = embed[(size_t)inds[n] * D_DIM + d];
    }
    __syncthreads();
    float* obase = out + (size_t)bb * D_DIM * N_DIM + n0;
    for (int i = threadIdx.x; i < 32 * D_DIM; i += 256) {
        int n = i & 31, d = i >> 5;
        obase[(size_t)d * N_DIM + n] = tile[n * 513 + d];
    }
}

// ---------------------------------------------------------------------------
extern "C" void kernel_launch(void* const* d_in, const int* in_sizes, int n_in,
                              void* d_out, int out_size) {
    const float* x     = (const float*)d_in[0];
    const float* embed = (const float*)d_in[1];
    float* out   = (float*)d_out;
    float* out_q = out;
    float* out_i = out + (size_t)B_DIM * D_DIM * N_DIM;
    (void)in_sizes; (void)n_in; (void)out_size;

    static const int gather_smem = 32 * 513 * (int)sizeof(float);
    static const int dist_smem = 2 * STAGE_BYTES;   // 96 KB
    cudaFuncSetAttribute(gather_kernel, cudaFuncAttributeMaxDynamicSharedMemorySize, gather_smem);
    cudaFuncSetAttribute(vq_dist_kernel, cudaFuncAttributeMaxDynamicSharedMemorySize, dist_smem);

    prep_embed_kernel<<<K_CB, 128>>>(embed);
    prep_x_kernel<<<dim3(N_DIM / 64, B_DIM), 256>>>(x);
    vq_dist_kernel<<<M_ROWS / 128, 256, dist_smem>>>(out_i);
    fallback_kernel<<<512, 256>>>(x, embed, out_i);
    gather_kernel<<<dim3(N_DIM / 32, B_DIM), 256, gather_smem>>>(embed, out_q);
}

// round 5
// speedup vs baseline: 2.6895x; 1.1573x over previous
#include <cuda_runtime.h>
#include <cuda_bf16.h>
#include <cstdint>
#include <cstddef>

#define K_CB   2048
#define D_DIM  512
#define B_DIM  16
#define N_DIM  8192
#define M_ROWS (B_DIM * N_DIM)
#define MARGIN 2.0e-3f

// -------- device scratch: separate hi/lo bf16 planes, packed in dim-pairs ----
// word j of a row = bf16(dim 2j) | bf16(dim 2j+1) << 16
__device__ uint32_t g_Ah[(size_t)M_ROWS * 256];
__device__ uint32_t g_Al[(size_t)M_ROWS * 256];
__device__ uint32_t g_Bh[(size_t)K_CB * 256];
__device__ uint32_t g_Bl[(size_t)K_CB * 256];
__device__ float    g_e2[K_CB];
__device__ int      g_ind[M_ROWS];
__device__ int      g_flag[M_ROWS];
__device__ int      g_nflag;

// -------- helpers --------
__device__ __forceinline__ uint32_t smem_u32(const void* p) {
    uint32_t a;
    asm("{ .reg .u64 t; cvta.to.shared.u64 t, %1; cvt.u32.u64 %0, t; }" : "=r"(a) : "l"(p));
    return a;
}
#define CP_A16(s, g) \
    asm volatile("cp.async.cg.shared.global [%0], [%1], 16;" :: "r"(s), "l"(g) : "memory")
#define CP_COMMIT() asm volatile("cp.async.commit_group;" ::: "memory")
#define CP_WAIT(n)  asm volatile("cp.async.wait_group %0;" :: "n"(n) : "memory")

__device__ __forceinline__ void ldsm4(uint32_t* r, uint32_t addr) {
    asm volatile("ldmatrix.sync.aligned.m8n8.x4.shared.b16 {%0,%1,%2,%3}, [%4];"
                 : "=r"(r[0]), "=r"(r[1]), "=r"(r[2]), "=r"(r[3]) : "r"(addr));
}
__device__ __forceinline__ void mma16816(float* c, const uint32_t* a, const uint32_t* b) {
    asm volatile("mma.sync.aligned.m16n8k16.row.col.f32.bf16.bf16.f32 "
                 "{%0,%1,%2,%3}, {%4,%5,%6,%7}, {%8,%9}, {%0,%1,%2,%3};"
                 : "+f"(c[0]), "+f"(c[1]), "+f"(c[2]), "+f"(c[3])
                 : "r"(a[0]), "r"(a[1]), "r"(a[2]), "r"(a[3]), "r"(b[0]), "r"(b[1]));
}
__device__ __forceinline__ uint32_t bf16hi(float v) {
    return (uint32_t)__bfloat16_as_ushort(__float2bfloat16(v));
}
__device__ __forceinline__ uint32_t bf16lo(float v) {
    float hf = __bfloat162float(__float2bfloat16(v));
    return (uint32_t)__bfloat16_as_ushort(__float2bfloat16(v - hf));
}

// -------- prep: codebook hi/lo planes + e2 --------
__global__ __launch_bounds__(128) void prep_embed_kernel(const float* __restrict__ embed) {
    int k = blockIdx.x;
    const float* row = embed + (size_t)k * D_DIM;
    uint32_t* bh = g_Bh + (size_t)k * 256;
    uint32_t* bl = g_Bl + (size_t)k * 256;
    float s = 0.f;
    for (int j = threadIdx.x; j < 256; j += 128) {
        float v0 = row[2 * j], v1 = row[2 * j + 1];
        s += v0 * v0 + v1 * v1;
        bh[j] = bf16hi(v0) | (bf16hi(v1) << 16);
        bl[j] = bf16lo(v0) | (bf16lo(v1) << 16);
    }
    #pragma unroll
    for (int o = 16; o > 0; o >>= 1) s += __shfl_down_sync(0xffffffffu, s, o);
    __shared__ float ws[4];
    if ((threadIdx.x & 31) == 0) ws[threadIdx.x >> 5] = s;
    __syncthreads();
    if (threadIdx.x == 0) g_e2[k] = ws[0] + ws[1] + ws[2] + ws[3];
    if (blockIdx.x == 0 && threadIdx.x == 0) g_nflag = 0;
}

// -------- prep: x[B,D,N] -> row-major hi/lo planes (transpose through smem) --
__global__ __launch_bounds__(256) void prep_x_kernel(const float* __restrict__ x) {
    __shared__ uint32_t t[64][65];   // per-dim packed (hi | lo<<16)
    int b = blockIdx.y, n0 = blockIdx.x * 64;
    const float* xb = x + (size_t)b * D_DIM * N_DIM + n0;
    for (int dc = 0; dc < 8; dc++) {
        __syncthreads();
        #pragma unroll
        for (int l = 0; l < 16; l++) {
            int i = threadIdx.x + l * 256;
            int dd = i >> 6, nn = i & 63;
            float v = xb[(size_t)(dc * 64 + dd) * N_DIM + nn];
            t[dd][nn] = bf16hi(v) | (bf16lo(v) << 16);
        }
        __syncthreads();
        #pragma unroll
        for (int l = 0; l < 8; l++) {
            int i = threadIdx.x + l * 256;
            int nn = i >> 5, jj = i & 31;
            uint32_t p0 = t[2 * jj][nn], p1 = t[2 * jj + 1][nn];
            size_t o = (size_t)(b * N_DIM + n0 + nn) * 256 + dc * 32 + jj;
            g_Ah[o] = (p0 & 0xffffu) | (p1 << 16);
            g_Al[o] = (p0 >> 16) | (p1 & 0xffff0000u);
        }
    }
}

// -------- tile loader: 4 x (128 rows x 128B), swizzled, via cp.async --------
#define STAGE_BYTES 65536
__device__ __forceinline__ void load_tiles(uint32_t ss, const uint4* Ah, const uint4* Al,
                                           const uint4* Bh, const uint4* Bl, int kb, int tid) {
    #pragma unroll
    for (int l = 0; l < 4; l++) {
        int i = tid + l * 256;
        int row = i >> 3, ch = i & 7;
        uint32_t soff = (uint32_t)row * 128 + (uint32_t)((ch ^ (row & 7)) << 4);
        size_t goff = (size_t)row * 64 + (size_t)kb * 8 + ch;
        CP_A16(ss + soff,         Ah + goff);
        CP_A16(ss + 16384 + soff, Al + goff);
        CP_A16(ss + 32768 + soff, Bh + goff);
        CP_A16(ss + 49152 + soff, Bl + goff);
    }
}

// -------- warp-tile compute: 32x64 per warp, 64 dims per stage, 3 products --
__device__ __forceinline__ void compute_stage(uint32_t ss, int lane, int wm, int wn,
                                              float acc[2][8][4]) {
    uint32_t sAh = ss, sAl = ss + 16384, sBh = ss + 32768, sBl = ss + 49152;
    #pragma unroll
    for (int kk = 0; kk < 4; kk++) {
        uint32_t ah[2][4], al[2][4];
        #pragma unroll
        for (int i = 0; i < 2; i++) {
            int r = wm * 32 + i * 16 + (lane & 15);
            int c = (kk * 2 + (lane >> 4)) ^ (r & 7);
            ldsm4(ah[i], sAh + r * 128 + c * 16);
            ldsm4(al[i], sAl + r * 128 + c * 16);
        }
        #pragma unroll
        for (int j16 = 0; j16 < 4; j16++) {
            int n = wn * 64 + j16 * 16 + (lane & 7) + ((lane >> 4) << 3);
            int c = (kk * 2 + ((lane >> 3) & 1)) ^ (n & 7);
            uint32_t bh[4], bl[4];
            ldsm4(bh, sBh + n * 128 + c * 16);
            ldsm4(bl, sBl + n * 128 + c * 16);
            #pragma unroll
            for (int i = 0; i < 2; i++) {
                mma16816(acc[i][j16 * 2 + 0], ah[i], bh + 0);
                mma16816(acc[i][j16 * 2 + 1], ah[i], bh + 2);
                mma16816(acc[i][j16 * 2 + 0], al[i], bh + 0);
                mma16816(acc[i][j16 * 2 + 1], al[i], bh + 2);
                mma16816(acc[i][j16 * 2 + 0], ah[i], bl + 0);
                mma16816(acc[i][j16 * 2 + 1], ah[i], bl + 2);
            }
        }
    }
}

// -------- main dist+argmax kernel --------
__global__ void __launch_bounds__(256) vq_dist_kernel(float* __restrict__ out_ind_f) {
    extern __shared__ char smem[];
    __shared__ float sB1[2][128];
    __shared__ float sB2[2][128];
    __shared__ int   sIx[2][128];
    uint32_t sb = smem_u32(smem);
    const int tid = threadIdx.x, lane = tid & 31, wid = tid >> 5;
    const int wm = wid & 3, wn = wid >> 2;
    const int m0 = blockIdx.x * 128;
    const uint4* Ah = (const uint4*)(g_Ah + (size_t)m0 * 256);
    const uint4* Al = (const uint4*)(g_Al + (size_t)m0 * 256);

    float best1[4], best2[4];
    int   bidx[4];
    #pragma unroll
    for (int r = 0; r < 4; r++) { best1[r] = -3.0e38f; best2[r] = -3.0e38f; bidx[r] = 0; }

    for (int nt = 0; nt < 16; nt++) {
        const uint4* Bh = (const uint4*)(g_Bh + (size_t)nt * 128 * 256);
        const uint4* Bl = (const uint4*)(g_Bl + (size_t)nt * 128 * 256);

        float acc[2][8][4];
        #pragma unroll
        for (int i = 0; i < 2; i++)
            #pragma unroll
            for (int j = 0; j < 8; j++)
                #pragma unroll
                for (int q = 0; q < 4; q++) acc[i][j][q] = 0.f;

        load_tiles(sb, Ah, Al, Bh, Bl, 0, tid);
        CP_COMMIT();
        for (int kb = 0; kb < 8; kb++) {
            uint32_t cur = sb + (kb & 1) * STAGE_BYTES;
            if (kb < 7) {
                load_tiles(sb + ((kb + 1) & 1) * STAGE_BYTES, Ah, Al, Bh, Bl, kb + 1, tid);
                CP_COMMIT();
                CP_WAIT(1);
            } else {
                CP_WAIT(0);
            }
            __syncthreads();
            compute_stage(cur, lane, wm, wn, acc);
            __syncthreads();
        }

        // fold scores into running top-2 (ascending k => strict '>' keeps lowest idx)
        #pragma unroll
        for (int j = 0; j < 8; j++) {
            int kb_ = nt * 128 + wn * 64 + j * 8 + (lane & 3) * 2;
            float e2a = g_e2[kb_], e2b = g_e2[kb_ + 1];
            #pragma unroll
            for (int i = 0; i < 2; i++) {
                float s0 = 2.f * acc[i][j][0] - e2a;
                float s1 = 2.f * acc[i][j][1] - e2b;
                float s2 = 2.f * acc[i][j][2] - e2a;
                float s3 = 2.f * acc[i][j][3] - e2b;
                int r0 = i * 2, r1 = i * 2 + 1;
                if (s0 > best1[r0]) { best2[r0] = best1[r0]; best1[r0] = s0; bidx[r0] = kb_; }
                else if (s0 > best2[r0]) best2[r0] = s0;
                if (s1 > best1[r0]) { best2[r0] = best1[r0]; best1[r0] = s1; bidx[r0] = kb_ + 1; }
                else if (s1 > best2[r0]) best2[r0] = s1;
                if (s2 > best1[r1]) { best2[r1] = best1[r1]; best1[r1] = s2; bidx[r1] = kb_; }
                else if (s2 > best2[r1]) best2[r1] = s2;
                if (s3 > best1[r1]) { best2[r1] = best1[r1]; best1[r1] = s3; bidx[r1] = kb_ + 1; }
                else if (s3 > best2[r1]) best2[r1] = s3;
            }
        }
    }

    // reduce across the 4 lanes sharing each row
    #pragma unroll
    for (int o = 1; o < 4; o <<= 1) {
        #pragma unroll
        for (int r = 0; r < 4; r++) {
            float ob1 = __shfl_xor_sync(0xffffffffu, best1[r], o);
            float ob2 = __shfl_xor_sync(0xffffffffu, best2[r], o);
            int   oi  = __shfl_xor_sync(0xffffffffu, bidx[r], o);
            float nb2 = fmaxf(fminf(best1[r], ob1), fmaxf(best2[r], ob2));
            if (ob1 > best1[r] || (ob1 == best1[r] && oi < bidx[r])) {
                best1[r] = ob1; bidx[r] = oi;
            }
            best2[r] = nb2;
        }
    }
    if ((lane & 3) == 0) {
        #pragma unroll
        for (int r = 0; r < 4; r++) {
            int row = wm * 32 + (r >> 1) * 16 + (r & 1) * 8 + (lane >> 2);
            sB1[wn][row] = best1[r];
            sB2[wn][row] = best2[r];
            sIx[wn][row] = bidx[r];
        }
    }
    __syncthreads();
    if (tid < 128) {
        float a1 = sB1[0][tid], b1 = sB1[1][tid];
        float a2 = sB2[0][tid], b2 = sB2[1][tid];
        int   ai = sIx[0][tid], bi = sIx[1][tid];
        float f2 = fmaxf(fminf(a1, b1), fmaxf(a2, b2));
        float f1; int fi;
        if (b1 > a1 || (b1 == a1 && bi < ai)) { f1 = b1; fi = bi; }
        else { f1 = a1; fi = ai; }
        int m = m0 + tid;
        g_ind[m] = fi;
        out_ind_f[m] = (float)fi;
        if (f1 - f2 < MARGIN) {
            int slot = atomicAdd(&g_nflag, 1);
            g_flag[slot] = m;
        }
    }
}

// -------- exact fp32 fallback for flagged rows --------
__global__ __launch_bounds__(256) void fallback_kernel(const float* __restrict__ x,
                                                       const float* __restrict__ embed,
                                                       float* __restrict__ out_ind_f) {
    __shared__ float xr[D_DIM];
    __shared__ float wbest[8];
    __shared__ int   widx[8];
    int nf = g_nflag;
    for (int f = blockIdx.x; f < nf; f += gridDim.x) {
        int m = g_flag[f];
        int b = m / N_DIM, n = m % N_DIM;
        for (int d = threadIdx.x; d < D_DIM; d += 256)
            xr[d] = x[(size_t)b * D_DIM * N_DIM + (size_t)d * N_DIM + n];
        __syncthreads();
        int wd = threadIdx.x >> 5, ld = threadIdx.x & 31;
        float best = -3.0e38f; int bi = 0;
        for (int k = wd; k < K_CB; k += 8) {
            const float* er = embed + (size_t)k * D_DIM;
            float s = 0.f;
            for (int d = ld; d < D_DIM; d += 32) s += xr[d] * er[d];
            #pragma unroll
            for (int o = 16; o > 0; o >>= 1) s += __shfl_down_sync(0xffffffffu, s, o);
            s = __shfl_sync(0xffffffffu, s, 0);
            float sc = 2.0f * s - g_e2[k];
            if (sc > best) { best = sc; bi = k; }
        }
        if (ld == 0) { wbest[wd] = best; widx[wd] = bi; }
        __syncthreads();
        if (threadIdx.x == 0) {
            float bv = wbest[0]; int bix = widx[0];
            #pragma unroll
            for (int w = 1; w < 8; w++)
                if (wbest[w] > bv || (wbest[w] == bv && widx[w] < bix)) { bv = wbest[w]; bix = widx[w]; }
            g_ind[m] = bix;
            out_ind_f[m] = (float)bix;
        }
        __syncthreads();
    }
}

// -------- gather: out[b,d,n] = embed[ind[b,n], d] --------
__global__ __launch_bounds__(256) void gather_kernel(const float* __restrict__ embed,
                                                     float* __restrict__ out) {
    extern __shared__ float tile[];
    __shared__ int inds[32];
    const int bb = blockIdx.y;
    const int n0 = blockIdx.x * 32;
    if (threadIdx.x < 32) inds[threadIdx.x] = g_ind[bb * N_DIM + n0 + threadIdx.x];
    __syncthreads();
    for (int i = threadIdx.x; i < 32 * D_DIM; i += 256) {
        int n = i >> 9, d = i & (D_DIM - 1);
        tile[n * 513 + d] = embed[(size_t)inds[n] * D_DIM + d];
    }
    __syncthreads();
    float* obase = out + (size_t)bb * D_DIM * N_DIM + n0;
    for (int i = threadIdx.x; i < 32 * D_DIM; i += 256) {
        int n = i & 31, d = i >> 5;
        obase[(size_t)d * N_DIM + n] = tile[n * 513 + d];
    }
}

// ---------------------------------------------------------------------------
extern "C" void kernel_launch(void* const* d_in, const int* in_sizes, int n_in,
                              void* d_out, int out_size) {
    const float* x     = (const float*)d_in[0];
    const float* embed = (const float*)d_in[1];
    float* out   = (float*)d_out;
    float* out_q = out;
    float* out_i = out + (size_t)B_DIM * D_DIM * N_DIM;
    (void)in_sizes; (void)n_in; (void)out_size;

    static const int gather_smem = 32 * 513 * (int)sizeof(float);
    static const int dist_smem = 2 * STAGE_BYTES;   // 128 KB
    cudaFuncSetAttribute(gather_kernel, cudaFuncAttributeMaxDynamicSharedMemorySize, gather_smem);
    cudaFuncSetAttribute(vq_dist_kernel, cudaFuncAttributeMaxDynamicSharedMemorySize, dist_smem);

    prep_embed_kernel<<<K_CB, 128>>>(embed);
    prep_x_kernel<<<dim3(N_DIM / 64, B_DIM), 256>>>(x);
    vq_dist_kernel<<<M_ROWS / 128, 256, dist_smem>>>(out_i);
    fallback_kernel<<<512, 256>>>(x, embed, out_i);
    gather_kernel<<<dim3(N_DIM / 32, B_DIM), 256, gather_smem>>>(embed, out_q);
}